// round 6
// baseline (speedup 1.0000x reference)
#include <cuda_runtime.h>
#include <cuda_bf16.h>
#include <mma.h>
#include <cstdint>

using namespace nvcuda;

// Problem constants
#define B       4
#define NSEQ    4096
#define DIM     1024
#define HEADS   8
#define DH      64
#define INNER   512          // HEADS*DH
#define M_ROWS  (B*NSEQ)     // 16384
#define N_QKV   (3*INNER)    // 1536
#define NCHUNK  8            // split-K chunks for context
#define ROWS_PER_CHUNK (NSEQ/NCHUNK)  // 512

// Scratch (device globals; no allocation allowed)
__device__ float g_qkv [(size_t)M_ROWS * N_QKV];          // ~100.7 MB
__device__ float g_ctxp[NCHUNK * B*HEADS * DH * DH];      // 4 MB
__device__ float g_attn[(size_t)M_ROWS * INNER];          // ~33.5 MB

// ---------------------------------------------------------------------------
// TF32 tensor-core GEMM (NT): C[M,N] = A[M,K] @ Bm[N,K]^T (+ bias[N])
// BM=BN=128, BK=32, 256 threads (8 warps as 2x4), warp tile 64x32,
// wmma 16x16x8 tf32 fragments, fp32 accumulate.
// Software-pipelined: double-buffered smem, prefetch chunk k+1 during
// compute of chunk k, ONE __syncthreads per chunk.
// Requires M%128==0, N%128==0, K%32==0.
// ---------------------------------------------------------------------------
#define BKP 40   // smem row stride (pad vs 32 for bank spread)

__global__ __launch_bounds__(256) void tf32_gemm_nt(
    const float* __restrict__ A,
    const float* __restrict__ Bm,
    float* __restrict__ C,
    const float* __restrict__ bias,
    int M, int N, int K)
{
    __shared__ __align__(16) float As[2][128][BKP];
    __shared__ __align__(16) float Bs[2][128][BKP];
    __shared__ __align__(16) float biasT[128][8];

    const int bm  = blockIdx.y * 128;
    const int bn  = blockIdx.x * 128;
    const int tid = threadIdx.x;
    const int wid = tid >> 5;
    const int wm  = (wid >> 2) * 64;   // warp row offset: 0 or 64
    const int wn  = (wid & 3) * 32;    // warp col offset: 0..96

    // per-thread staging coords: 4 float4 per operand per chunk
    const int sr = tid >> 3;           // row 0..31 (x8 strided by 32? no: see below)
    const int sc = (tid & 7) * 4;      // col 0..28

    wmma::fragment<wmma::accumulator, 16, 16, 8, float> acc[4][2];
    #pragma unroll
    for (int mi = 0; mi < 4; mi++)
        #pragma unroll
        for (int ni = 0; ni < 2; ni++)
            wmma::fill_fragment(acc[mi][ni], 0.0f);

    // ---- fold bias into accumulators: acc += ones(0.125) @ biasT (8 k-terms)
    if (bias) {
        if (tid < 128) {
            float bv = bias[bn + tid];
            #pragma unroll
            for (int k = 0; k < 8; k++) biasT[tid][k] = bv;
        }
        __syncthreads();
        wmma::fragment<wmma::matrix_a, 16, 16, 8, wmma::precision::tf32,
                       wmma::row_major> af;
        wmma::fill_fragment(af, wmma::__float_to_tf32(0.125f));
        #pragma unroll
        for (int ni = 0; ni < 2; ni++) {
            wmma::fragment<wmma::matrix_b, 16, 16, 8, wmma::precision::tf32,
                           wmma::col_major> bf;
            wmma::load_matrix_sync(bf, &biasT[wn + ni * 16][0], 8);
            #pragma unroll
            for (int t = 0; t < bf.num_elements; t++)
                bf.x[t] = wmma::__float_to_tf32(bf.x[t]);
            #pragma unroll
            for (int mi = 0; mi < 4; mi++)
                wmma::mma_sync(acc[mi][ni], af, bf, acc[mi][ni]);
        }
        __syncthreads();
    }

    const float* Aptr = A  + (size_t)bm * K;
    const float* Bptr = Bm + (size_t)bn * K;
    const int nk = K >> 5;

    float4 ar[4], br[4];

    // ---- prologue: load + stage chunk 0
    #pragma unroll
    for (int i = 0; i < 4; i++) {
        int r = sr + i * 32;
        ar[i] = *(const float4*)(Aptr + (size_t)r * K + sc);
        br[i] = *(const float4*)(Bptr + (size_t)r * K + sc);
    }
    #pragma unroll
    for (int i = 0; i < 4; i++) {
        int r = sr + i * 32;
        As[0][r][sc+0] = wmma::__float_to_tf32(ar[i].x);
        As[0][r][sc+1] = wmma::__float_to_tf32(ar[i].y);
        As[0][r][sc+2] = wmma::__float_to_tf32(ar[i].z);
        As[0][r][sc+3] = wmma::__float_to_tf32(ar[i].w);
        Bs[0][r][sc+0] = wmma::__float_to_tf32(br[i].x);
        Bs[0][r][sc+1] = wmma::__float_to_tf32(br[i].y);
        Bs[0][r][sc+2] = wmma::__float_to_tf32(br[i].z);
        Bs[0][r][sc+3] = wmma::__float_to_tf32(br[i].w);
    }
    __syncthreads();

    for (int kc = 0; kc < nk; kc++) {
        const int cur = kc & 1;
        const int nxt = cur ^ 1;

        // ---- prefetch chunk kc+1 into registers (latency covered by MMAs)
        const bool have_next = (kc + 1) < nk;
        if (have_next) {
            const float* Ap = Aptr + (kc + 1) * 32;
            const float* Bp = Bptr + (kc + 1) * 32;
            #pragma unroll
            for (int i = 0; i < 4; i++) {
                int r = sr + i * 32;
                ar[i] = *(const float4*)(Ap + (size_t)r * K + sc);
                br[i] = *(const float4*)(Bp + (size_t)r * K + sc);
            }
        }

        // ---- compute chunk kc from smem[cur]
        #pragma unroll
        for (int ks = 0; ks < 4; ks++) {
            wmma::fragment<wmma::matrix_a, 16, 16, 8, wmma::precision::tf32,
                           wmma::row_major> af[4];
            wmma::fragment<wmma::matrix_b, 16, 16, 8, wmma::precision::tf32,
                           wmma::col_major> bf[2];
            #pragma unroll
            for (int mi = 0; mi < 4; mi++)
                wmma::load_matrix_sync(af[mi], &As[cur][wm + mi * 16][ks * 8], BKP);
            #pragma unroll
            for (int ni = 0; ni < 2; ni++)
                wmma::load_matrix_sync(bf[ni], &Bs[cur][wn + ni * 16][ks * 8], BKP);
            #pragma unroll
            for (int mi = 0; mi < 4; mi++)
                #pragma unroll
                for (int ni = 0; ni < 2; ni++)
                    wmma::mma_sync(acc[mi][ni], af[mi], bf[ni], acc[mi][ni]);
        }

        // ---- stage chunk kc+1 into smem[nxt]
        if (have_next) {
            #pragma unroll
            for (int i = 0; i < 4; i++) {
                int r = sr + i * 32;
                As[nxt][r][sc+0] = wmma::__float_to_tf32(ar[i].x);
                As[nxt][r][sc+1] = wmma::__float_to_tf32(ar[i].y);
                As[nxt][r][sc+2] = wmma::__float_to_tf32(ar[i].z);
                As[nxt][r][sc+3] = wmma::__float_to_tf32(ar[i].w);
                Bs[nxt][r][sc+0] = wmma::__float_to_tf32(br[i].x);
                Bs[nxt][r][sc+1] = wmma::__float_to_tf32(br[i].y);
                Bs[nxt][r][sc+2] = wmma::__float_to_tf32(br[i].z);
                Bs[nxt][r][sc+3] = wmma::__float_to_tf32(br[i].w);
            }
        }
        __syncthreads();
    }

    #pragma unroll
    for (int mi = 0; mi < 4; mi++)
        #pragma unroll
        for (int ni = 0; ni < 2; ni++)
            wmma::store_matrix_sync(
                &C[(size_t)(bm + wm + mi * 16) * N + bn + wn + ni * 16],
                acc[mi][ni], N, wmma::mem_row_major);
}

// ---------------------------------------------------------------------------
// Context kernel: for each (b,h), ctx[d][e] = sum_n softmax(k[n,:])[d] * v[n,e]
// Split over n into NCHUNK chunks; deterministic partials. grid=(32,NCHUNK).
// ---------------------------------------------------------------------------
__global__ __launch_bounds__(256) void ctx_kernel()
{
    const int pair  = blockIdx.x;
    const int chunk = blockIdx.y;
    const int b = pair >> 3, h = pair & 7;
    const int tid = threadIdx.x;

    __shared__ __align__(16) float sk[32][DH];
    __shared__ __align__(16) float sv[32][DH];

    const int d0 = (tid >> 4) * 4;
    const int e0 = (tid & 15) * 4;

    float acc[4][4];
    #pragma unroll
    for (int i = 0; i < 4; i++)
        #pragma unroll
        for (int j = 0; j < 4; j++) acc[i][j] = 0.f;

    const float* base = g_qkv + (size_t)b * NSEQ * N_QKV;
    const int n_begin = chunk * ROWS_PER_CHUNK;

    for (int n0 = n_begin; n0 < n_begin + ROWS_PER_CHUNK; n0 += 32) {
        #pragma unroll
        for (int i = 0; i < 2; i++) {
            int id = tid + i * 256;
            int r  = id >> 4;
            int c  = (id & 15) * 4;
            size_t off = (size_t)(n0 + r) * N_QKV + h * DH + c;
            *(float4*)&sk[r][c] = *(const float4*)(base + off + INNER);
            *(float4*)&sv[r][c] = *(const float4*)(base + off + 2 * INNER);
        }
        __syncthreads();

        {
            int r     = tid >> 3;
            int lane8 = tid & 7;
            float vals[8];
            float m = -1e30f;
            #pragma unroll
            for (int j = 0; j < 8; j++) {
                vals[j] = sk[r][lane8 * 8 + j];
                m = fmaxf(m, vals[j]);
            }
            #pragma unroll
            for (int s = 4; s >= 1; s >>= 1)
                m = fmaxf(m, __shfl_xor_sync(0xffffffffu, m, s));
            float sum = 0.f;
            #pragma unroll
            for (int j = 0; j < 8; j++) { vals[j] = __expf(vals[j] - m); sum += vals[j]; }
            #pragma unroll
            for (int s = 4; s >= 1; s >>= 1)
                sum += __shfl_xor_sync(0xffffffffu, sum, s);
            float inv = 1.0f / sum;
            #pragma unroll
            for (int j = 0; j < 8; j++)
                sk[r][lane8 * 8 + j] = vals[j] * inv;
        }
        __syncthreads();

        #pragma unroll 4
        for (int r = 0; r < 32; r++) {
            float4 kd = *(const float4*)&sk[r][d0];
            float4 ve = *(const float4*)&sv[r][e0];
            float kdv[4] = {kd.x, kd.y, kd.z, kd.w};
            float vev[4] = {ve.x, ve.y, ve.z, ve.w};
            #pragma unroll
            for (int i = 0; i < 4; i++)
                #pragma unroll
                for (int j = 0; j < 4; j++)
                    acc[i][j] += kdv[i] * vev[j];
        }
        __syncthreads();
    }

    float* out = g_ctxp + ((size_t)chunk * (B*HEADS) + pair) * DH * DH;
    #pragma unroll
    for (int i = 0; i < 4; i++) {
        float4 v = make_float4(acc[i][0], acc[i][1], acc[i][2], acc[i][3]);
        *(float4*)&out[(d0 + i) * DH + e0] = v;
    }
}

// ---------------------------------------------------------------------------
// Attention-apply: attn[b,n,h*64+e] = sum_d q[b,n,h*64+d] * ctx[b,h][d][e]
// grid = (32 pairs, 4096/128 row tiles), block = 256.
// ---------------------------------------------------------------------------
__global__ __launch_bounds__(256) void attn_kernel()
{
    const int pair = blockIdx.x;
    const int b = pair >> 3, h = pair & 7;
    const int n0 = blockIdx.y * 128;
    const int tid = threadIdx.x;

    __shared__ __align__(16) float sctx[DH][DH];
    __shared__ __align__(16) float sq[128][DH];

    for (int idx = tid; idx < DH * DH; idx += 256) {
        float s = 0.f;
        #pragma unroll
        for (int ch = 0; ch < NCHUNK; ch++)
            s += g_ctxp[((size_t)ch * (B*HEADS) + pair) * DH * DH + idx];
        sctx[idx >> 6][idx & 63] = s;
    }

    const float* qbase = g_qkv + (size_t)b * NSEQ * N_QKV + h * DH;
    #pragma unroll
    for (int i = 0; i < 8; i++) {
        int id = tid + i * 256;
        int r  = id >> 4;
        int c  = (id & 15) * 4;
        *(float4*)&sq[r][c] =
            *(const float4*)(qbase + (size_t)(n0 + r) * N_QKV + c);
    }
    __syncthreads();

    const int e0 = (tid & 15) * 4;
    const int rg = tid >> 4;
    float acc[8][4];
    #pragma unroll
    for (int i = 0; i < 8; i++)
        #pragma unroll
        for (int j = 0; j < 4; j++) acc[i][j] = 0.f;

    #pragma unroll 8
    for (int d = 0; d < DH; d++) {
        float4 c4 = *(const float4*)&sctx[d][e0];
        float cv[4] = {c4.x, c4.y, c4.z, c4.w};
        #pragma unroll
        for (int i = 0; i < 8; i++) {
            float a = sq[rg + 16 * i][d];
            #pragma unroll
            for (int j = 0; j < 4; j++)
                acc[i][j] += a * cv[j];
        }
    }

    float* obase = g_attn + (size_t)(b * NSEQ + n0) * INNER + h * DH;
    #pragma unroll
    for (int i = 0; i < 8; i++) {
        int r = rg + 16 * i;
        float4 v = make_float4(acc[i][0], acc[i][1], acc[i][2], acc[i][3]);
        *(float4*)(obase + (size_t)r * INNER + e0) = v;
    }
}

// ---------------------------------------------------------------------------
extern "C" void kernel_launch(void* const* d_in, const int* in_sizes, int n_in,
                              void* d_out, int out_size)
{
    const float* x     = (const float*)d_in[0];   // [4,4096,1024]
    const float* w_qkv = (const float*)d_in[1];   // [1536,1024]
    const float* w_out = (const float*)d_in[2];   // [1024,512]
    const float* b_out = (const float*)d_in[3];   // [1024]
    float* out = (float*)d_out;                   // [4,4096,1024]

    float *qkv_ptr, *attn_ptr;
    cudaGetSymbolAddress((void**)&qkv_ptr,  g_qkv);
    cudaGetSymbolAddress((void**)&attn_ptr, g_attn);

    // 1) QKV projection: [16384,1536] = x @ w_qkv^T   (tf32 mma.sync, pipelined)
    tf32_gemm_nt<<<dim3(N_QKV / 128, M_ROWS / 128), 256>>>(
        x, w_qkv, qkv_ptr, nullptr, M_ROWS, N_QKV, DIM);

    // 2) softmax(k) + context partials
    ctx_kernel<<<dim3(B * HEADS, NCHUNK), 256>>>();

    // 3) q @ context -> attn [16384, 512]
    attn_kernel<<<dim3(B * HEADS, NSEQ / 128), 256>>>();

    // 4) output projection + bias: [16384,1024] = attn @ w_out^T + b_out
    tf32_gemm_nt<<<dim3(DIM / 128, M_ROWS / 128), 256>>>(
        attn_ptr, w_out, out, b_out, M_ROWS, DIM, INNER);
}

// round 8
// speedup vs baseline: 1.5603x; 1.5603x over previous
#include <cuda_runtime.h>
#include <cuda_bf16.h>
#include <mma.h>
#include <cstdint>

using namespace nvcuda;

// Problem constants
#define B       4
#define NSEQ    4096
#define DIM     1024
#define HEADS   8
#define DH      64
#define INNER   512          // HEADS*DH
#define M_ROWS  (B*NSEQ)     // 16384
#define N_QKV   (3*INNER)    // 1536
#define NCHUNK  8
#define ROWS_PER_CHUNK (NSEQ/NCHUNK)  // 512

// Scratch (device globals; no allocation allowed)
__device__ float g_qkv  [(size_t)M_ROWS * N_QKV];     // ~100.7 MB
__device__ float g_ctxp [NCHUNK * B*HEADS * DH * DH]; // 4 MB
__device__ float g_attn [(size_t)M_ROWS * INNER];     // ~33.5 MB (tf32-rounded)
__device__ float g_xc   [(size_t)M_ROWS * DIM];       // 64 MB  (tf32-rounded x)
__device__ float g_wqkvc[(size_t)N_QKV * DIM];        // 6 MB
__device__ float g_woutc[(size_t)DIM * INNER];        // 2 MB

// ---------------------------------------------------------------------------
__device__ __forceinline__ float to_tf32(float x) {
    uint32_t u;
    asm("cvt.rna.tf32.f32 %0, %1;" : "=r"(u) : "f"(x));
    return __uint_as_float(u);
}
__device__ __forceinline__ uint32_t smem_u32(const void* p) {
    uint32_t a;
    asm("{ .reg .u64 t; cvta.to.shared.u64 t, %1; cvt.u32.u64 %0, t; }"
        : "=r"(a) : "l"(p));
    return a;
}
#define CP_ASYNC16(dst, src) \
    asm volatile("cp.async.cg.shared.global [%0], [%1], 16;" \
                 :: "r"(dst), "l"(src) : "memory")
#define CP_COMMIT() asm volatile("cp.async.commit_group;" ::: "memory")
#define CP_WAIT0()  asm volatile("cp.async.wait_group 0;" ::: "memory")
#define CP_WAIT1()  asm volatile("cp.async.wait_group 1;" ::: "memory")

// ---------------------------------------------------------------------------
// Pre-pass: round fp32 -> tf32 (RNA), vectorized
// ---------------------------------------------------------------------------
__global__ __launch_bounds__(256) void cvt_tf32_kernel(
    const float* __restrict__ src, float* __restrict__ dst, int n4)
{
    int i = blockIdx.x * 256 + threadIdx.x;
    if (i < n4) {
        float4 v = ((const float4*)src)[i];
        v.x = to_tf32(v.x); v.y = to_tf32(v.y);
        v.z = to_tf32(v.z); v.w = to_tf32(v.w);
        ((float4*)dst)[i] = v;
    }
}

// ---------------------------------------------------------------------------
// TF32 GEMM (NT): C[M,N] = A[M,K] @ Bm[N,K]^T (+ bias[N])
// Inputs pre-rounded to tf32. CTA tile 128x256, 8 warps (2x4), warp 64x64.
// BK=32, cp.async double-buffered, wmma m16n16k8 tf32.
// Requires M%128==0, N%256==0, K%32==0.
// ---------------------------------------------------------------------------
#define BKP 40                               // padded K stride (floats)
#define OFF_A0 0
#define OFF_A1 (128*BKP*4)                   // 20480
#define OFF_B0 (2*128*BKP*4)                 // 40960
#define OFF_B1 (OFF_B0 + 256*BKP*4)          // 81920
#define SMEM_GEMM (OFF_B1 + 256*BKP*4)       // 122880

__global__ __launch_bounds__(256) void tf32_gemm_cp(
    const float* __restrict__ A,
    const float* __restrict__ Bm,
    float* __restrict__ C,
    const float* __restrict__ bias,
    int M, int N, int K)
{
    extern __shared__ __align__(16) float smf[];
    const uint32_t sb = smem_u32(smf);
    const int tid = threadIdx.x;
    const int wid = tid >> 5;
    const int bm = blockIdx.y * 128;
    const int bn = blockIdx.x * 256;
    const int wm = (wid >> 2) * 64;          // 0 or 64
    const int wn = (wid & 3) * 64;           // 0..192

    wmma::fragment<wmma::accumulator, 16, 16, 8, float> acc[4][4];
    #pragma unroll
    for (int mi = 0; mi < 4; mi++)
        #pragma unroll
        for (int ni = 0; ni < 4; ni++)
            wmma::fill_fragment(acc[mi][ni], 0.0f);

    // ---- fold bias: acc += ones(0.125) @ biasT (8 k-terms, exact)
    if (bias) {
        float (*biasT)[8] = (float(*)[8])smf;    // 256x8, overlays buffers
        {
            float bv = bias[bn + tid];
            #pragma unroll
            for (int k = 0; k < 8; k++) biasT[tid][k] = bv;
        }
        __syncthreads();
        wmma::fragment<wmma::matrix_a, 16, 16, 8, wmma::precision::tf32,
                       wmma::row_major> af;
        wmma::fill_fragment(af, wmma::__float_to_tf32(0.125f));
        #pragma unroll
        for (int ni = 0; ni < 4; ni++) {
            wmma::fragment<wmma::matrix_b, 16, 16, 8, wmma::precision::tf32,
                           wmma::col_major> bf;
            wmma::load_matrix_sync(bf, &biasT[wn + ni * 16][0], 8);
            #pragma unroll
            for (int t = 0; t < bf.num_elements; t++)
                bf.x[t] = wmma::__float_to_tf32(bf.x[t]);
            #pragma unroll
            for (int mi = 0; mi < 4; mi++)
                wmma::mma_sync(acc[mi][ni], af, bf, acc[mi][ni]);
        }
        __syncthreads();
    }

    const float* Aptr = A  + (size_t)bm * K;
    const float* Bptr = Bm + (size_t)bn * K;
    const int nk = K >> 5;

    // per-thread cp.async coords
    const int sr = tid >> 3;                  // 0..31
    const int scol = (tid & 7) * 4;           // 0..28

    // issue one chunk's loads into buffer `buf`
    auto issue = [&](int kc, int buf) {
        const float* Ap = Aptr + kc * 32;
        const uint32_t abase = sb + (buf ? OFF_A1 : OFF_A0);
        #pragma unroll
        for (int i = 0; i < 4; i++) {
            int r = sr + i * 32;              // 0..127
            CP_ASYNC16(abase + (uint32_t)(r * BKP + scol) * 4,
                       Ap + (size_t)r * K + scol);
        }
        const float* Bp = Bptr + kc * 32;
        const uint32_t bbase = sb + (buf ? OFF_B1 : OFF_B0);
        #pragma unroll
        for (int i = 0; i < 8; i++) {
            int r = sr + i * 32;              // 0..255
            CP_ASYNC16(bbase + (uint32_t)(r * BKP + scol) * 4,
                       Bp + (size_t)r * K + scol);
        }
        CP_COMMIT();
    };

    issue(0, 0);

    for (int kc = 0; kc < nk; kc++) {
        const int cur = kc & 1;
        const bool hn = (kc + 1) < nk;
        if (hn) issue(kc + 1, cur ^ 1);
        if (hn) { CP_WAIT1(); } else { CP_WAIT0(); }
        __syncthreads();

        const float* Abuf = smf + (cur ? OFF_A1 : OFF_A0) / 4;
        const float* Bbuf = smf + (cur ? OFF_B1 : OFF_B0) / 4;

        #pragma unroll
        for (int ks = 0; ks < 4; ks++) {
            wmma::fragment<wmma::matrix_a, 16, 16, 8, wmma::precision::tf32,
                           wmma::row_major> af[4];
            wmma::fragment<wmma::matrix_b, 16, 16, 8, wmma::precision::tf32,
                           wmma::col_major> bf[4];
            #pragma unroll
            for (int mi = 0; mi < 4; mi++)
                wmma::load_matrix_sync(af[mi],
                    Abuf + (wm + mi * 16) * BKP + ks * 8, BKP);
            #pragma unroll
            for (int ni = 0; ni < 4; ni++)
                wmma::load_matrix_sync(bf[ni],
                    Bbuf + (wn + ni * 16) * BKP + ks * 8, BKP);
            #pragma unroll
            for (int mi = 0; mi < 4; mi++)
                #pragma unroll
                for (int ni = 0; ni < 4; ni++)
                    wmma::mma_sync(acc[mi][ni], af[mi], bf[ni], acc[mi][ni]);
        }
        __syncthreads();
    }

    #pragma unroll
    for (int mi = 0; mi < 4; mi++)
        #pragma unroll
        for (int ni = 0; ni < 4; ni++)
            wmma::store_matrix_sync(
                &C[(size_t)(bm + wm + mi * 16) * N + bn + wn + ni * 16],
                acc[mi][ni], N, wmma::mem_row_major);
}

// ---------------------------------------------------------------------------
// Context kernel: ctx[d][e] = sum_n softmax(k[n,:])[d] * v[n,e], split-K
// ---------------------------------------------------------------------------
__global__ __launch_bounds__(256) void ctx_kernel()
{
    const int pair  = blockIdx.x;
    const int chunk = blockIdx.y;
    const int b = pair >> 3, h = pair & 7;
    const int tid = threadIdx.x;

    __shared__ __align__(16) float sk[32][DH];
    __shared__ __align__(16) float sv[32][DH];

    const int d0 = (tid >> 4) * 4;
    const int e0 = (tid & 15) * 4;

    float acc[4][4];
    #pragma unroll
    for (int i = 0; i < 4; i++)
        #pragma unroll
        for (int j = 0; j < 4; j++) acc[i][j] = 0.f;

    const float* base = g_qkv + (size_t)b * NSEQ * N_QKV;
    const int n_begin = chunk * ROWS_PER_CHUNK;

    for (int n0 = n_begin; n0 < n_begin + ROWS_PER_CHUNK; n0 += 32) {
        #pragma unroll
        for (int i = 0; i < 2; i++) {
            int id = tid + i * 256;
            int r  = id >> 4;
            int c  = (id & 15) * 4;
            size_t off = (size_t)(n0 + r) * N_QKV + h * DH + c;
            *(float4*)&sk[r][c] = *(const float4*)(base + off + INNER);
            *(float4*)&sv[r][c] = *(const float4*)(base + off + 2 * INNER);
        }
        __syncthreads();

        {
            int r     = tid >> 3;
            int lane8 = tid & 7;
            float vals[8];
            float m = -1e30f;
            #pragma unroll
            for (int j = 0; j < 8; j++) {
                vals[j] = sk[r][lane8 * 8 + j];
                m = fmaxf(m, vals[j]);
            }
            #pragma unroll
            for (int s = 4; s >= 1; s >>= 1)
                m = fmaxf(m, __shfl_xor_sync(0xffffffffu, m, s));
            float sum = 0.f;
            #pragma unroll
            for (int j = 0; j < 8; j++) { vals[j] = __expf(vals[j] - m); sum += vals[j]; }
            #pragma unroll
            for (int s = 4; s >= 1; s >>= 1)
                sum += __shfl_xor_sync(0xffffffffu, sum, s);
            float inv = 1.0f / sum;
            #pragma unroll
            for (int j = 0; j < 8; j++)
                sk[r][lane8 * 8 + j] = vals[j] * inv;
        }
        __syncthreads();

        #pragma unroll 4
        for (int r = 0; r < 32; r++) {
            float4 kd = *(const float4*)&sk[r][d0];
            float4 ve = *(const float4*)&sv[r][e0];
            float kdv[4] = {kd.x, kd.y, kd.z, kd.w};
            float vev[4] = {ve.x, ve.y, ve.z, ve.w};
            #pragma unroll
            for (int i = 0; i < 4; i++)
                #pragma unroll
                for (int j = 0; j < 4; j++)
                    acc[i][j] += kdv[i] * vev[j];
        }
        __syncthreads();
    }

    float* out = g_ctxp + ((size_t)chunk * (B*HEADS) + pair) * DH * DH;
    #pragma unroll
    for (int i = 0; i < 4; i++) {
        float4 v = make_float4(acc[i][0], acc[i][1], acc[i][2], acc[i][3]);
        *(float4*)&out[(d0 + i) * DH + e0] = v;
    }
}

// ---------------------------------------------------------------------------
// Attention-apply; output rounded to tf32 (feeds GEMM4 directly)
// ---------------------------------------------------------------------------
__global__ __launch_bounds__(256) void attn_kernel()
{
    const int pair = blockIdx.x;
    const int b = pair >> 3, h = pair & 7;
    const int n0 = blockIdx.y * 128;
    const int tid = threadIdx.x;

    __shared__ __align__(16) float sctx[DH][DH];
    __shared__ __align__(16) float sq[128][DH];

    for (int idx = tid; idx < DH * DH; idx += 256) {
        float s = 0.f;
        #pragma unroll
        for (int ch = 0; ch < NCHUNK; ch++)
            s += g_ctxp[((size_t)ch * (B*HEADS) + pair) * DH * DH + idx];
        sctx[idx >> 6][idx & 63] = s;
    }

    const float* qbase = g_qkv + (size_t)b * NSEQ * N_QKV + h * DH;
    #pragma unroll
    for (int i = 0; i < 8; i++) {
        int id = tid + i * 256;
        int r  = id >> 4;
        int c  = (id & 15) * 4;
        *(float4*)&sq[r][c] =
            *(const float4*)(qbase + (size_t)(n0 + r) * N_QKV + c);
    }
    __syncthreads();

    const int e0 = (tid & 15) * 4;
    const int rg = tid >> 4;
    float acc[8][4];
    #pragma unroll
    for (int i = 0; i < 8; i++)
        #pragma unroll
        for (int j = 0; j < 4; j++) acc[i][j] = 0.f;

    #pragma unroll 8
    for (int d = 0; d < DH; d++) {
        float4 c4 = *(const float4*)&sctx[d][e0];
        float cv[4] = {c4.x, c4.y, c4.z, c4.w};
        #pragma unroll
        for (int i = 0; i < 8; i++) {
            float a = sq[rg + 16 * i][d];
            #pragma unroll
            for (int j = 0; j < 4; j++)
                acc[i][j] += a * cv[j];
        }
    }

    float* obase = g_attn + (size_t)(b * NSEQ + n0) * INNER + h * DH;
    #pragma unroll
    for (int i = 0; i < 8; i++) {
        int r = rg + 16 * i;
        float4 v = make_float4(to_tf32(acc[i][0]), to_tf32(acc[i][1]),
                               to_tf32(acc[i][2]), to_tf32(acc[i][3]));
        *(float4*)(obase + (size_t)r * INNER + e0) = v;
    }
}

// ---------------------------------------------------------------------------
extern "C" void kernel_launch(void* const* d_in, const int* in_sizes, int n_in,
                              void* d_out, int out_size)
{
    const float* x     = (const float*)d_in[0];   // [4,4096,1024]
    const float* w_qkv = (const float*)d_in[1];   // [1536,1024]
    const float* w_out = (const float*)d_in[2];   // [1024,512]
    const float* b_out = (const float*)d_in[3];   // [1024]
    float* out = (float*)d_out;                   // [4,4096,1024]

    float *qkv_p, *attn_p, *xc_p, *wqkvc_p, *woutc_p;
    cudaGetSymbolAddress((void**)&qkv_p,   g_qkv);
    cudaGetSymbolAddress((void**)&attn_p,  g_attn);
    cudaGetSymbolAddress((void**)&xc_p,    g_xc);
    cudaGetSymbolAddress((void**)&wqkvc_p, g_wqkvc);
    cudaGetSymbolAddress((void**)&woutc_p, g_woutc);

    cudaFuncSetAttribute(tf32_gemm_cp,
        cudaFuncAttributeMaxDynamicSharedMemorySize, SMEM_GEMM);

    // 0) round inputs to tf32 once (streaming, ~30us total)
    {
        int n4x = M_ROWS * DIM / 4;
        cvt_tf32_kernel<<<(n4x + 255) / 256, 256>>>(x, xc_p, n4x);
        int n4q = N_QKV * DIM / 4;
        cvt_tf32_kernel<<<(n4q + 255) / 256, 256>>>(w_qkv, wqkvc_p, n4q);
        int n4o = DIM * INNER / 4;
        cvt_tf32_kernel<<<(n4o + 255) / 256, 256>>>(w_out, woutc_p, n4o);
    }

    // 1) QKV projection: [16384,1536] = xc @ wqkvc^T
    tf32_gemm_cp<<<dim3(N_QKV / 256, M_ROWS / 128), 256, SMEM_GEMM>>>(
        xc_p, wqkvc_p, qkv_p, nullptr, M_ROWS, N_QKV, DIM);

    // 2) softmax(k) + context partials
    ctx_kernel<<<dim3(B * HEADS, NCHUNK), 256>>>();

    // 3) q @ context -> attn (tf32-rounded) [16384, 512]
    attn_kernel<<<dim3(B * HEADS, NSEQ / 128), 256>>>();

    // 4) output projection + bias: [16384,1024] = attn @ woutc^T + b_out
    tf32_gemm_cp<<<dim3(DIM / 256, M_ROWS / 128), 256, SMEM_GEMM>>>(
        attn_p, woutc_p, out, b_out, M_ROWS, DIM, INNER);
}

// round 10
// speedup vs baseline: 1.6032x; 1.0275x over previous
#include <cuda_runtime.h>
#include <cuda_bf16.h>
#include <mma.h>
#include <cstdint>

using namespace nvcuda;

// Problem constants
#define B       4
#define NSEQ    4096
#define DIM     1024
#define HEADS   8
#define DH      64
#define INNER   512          // HEADS*DH
#define M_ROWS  (B*NSEQ)     // 16384
#define N_QKV   (3*INNER)    // 1536
#define NCHUNK  8
#define ROWS_PER_CHUNK (NSEQ/NCHUNK)  // 512

// Scratch (device globals; no allocation allowed)
__device__ float g_qkv  [(size_t)M_ROWS * N_QKV];     // ~100.7 MB
__device__ float g_ctxp [NCHUNK * B*HEADS * DH * DH]; // 4 MB
__device__ float g_attn [(size_t)M_ROWS * INNER];     // ~33.5 MB (tf32-rounded)
__device__ float g_xc   [(size_t)M_ROWS * DIM];       // 64 MB  (tf32-rounded x)
__device__ float g_wqkvc[(size_t)N_QKV * DIM];        // 6 MB
__device__ float g_woutc[(size_t)DIM * INNER];        // 2 MB

// ---------------------------------------------------------------------------
__device__ __forceinline__ float to_tf32(float x) {
    uint32_t u;
    asm("cvt.rna.tf32.f32 %0, %1;" : "=r"(u) : "f"(x));
    return __uint_as_float(u);
}
__device__ __forceinline__ uint32_t smem_u32(const void* p) {
    uint32_t a;
    asm("{ .reg .u64 t; cvta.to.shared.u64 t, %1; cvt.u32.u64 %0, t; }"
        : "=r"(a) : "l"(p));
    return a;
}
#define CP_ASYNC16(dst, src) \
    asm volatile("cp.async.cg.shared.global [%0], [%1], 16;" \
                 :: "r"(dst), "l"(src) : "memory")
#define CP_COMMIT() asm volatile("cp.async.commit_group;" ::: "memory")
#define CP_WAIT0()  asm volatile("cp.async.wait_group 0;" ::: "memory")
#define CP_WAIT1()  asm volatile("cp.async.wait_group 1;" ::: "memory")

// ---------------------------------------------------------------------------
// Pre-pass: round fp32 -> tf32 (RNA), vectorized
// ---------------------------------------------------------------------------
__global__ __launch_bounds__(256) void cvt_tf32_kernel(
    const float* __restrict__ src, float* __restrict__ dst, int n4)
{
    int i = blockIdx.x * 256 + threadIdx.x;
    if (i < n4) {
        float4 v = ((const float4*)src)[i];
        v.x = to_tf32(v.x); v.y = to_tf32(v.y);
        v.z = to_tf32(v.z); v.w = to_tf32(v.w);
        ((float4*)dst)[i] = v;
    }
}

// ---------------------------------------------------------------------------
// TF32 GEMM (NT): C[M,N] = A[M,K] @ Bm[N,K]^T (+ bias[N])
// Inputs pre-rounded to tf32. CTA tile 128x256, 8 warps (2x4), warp 64x64.
// BK=64, cp.async double-buffered (two 108KB stages), wmma m16n16k8 tf32.
// Requires M%128==0, N%256==0, K%64==0.
// ---------------------------------------------------------------------------
#define BKQ 64                               // K per chunk
#define BKP 72                               // padded K stride (floats)
#define OFF_A0 0
#define OFF_A1 (128*BKP*4)                   // 36864
#define OFF_B0 (2*128*BKP*4)                 // 73728
#define OFF_B1 (OFF_B0 + 256*BKP*4)          // 147456
#define SMEM_GEMM (OFF_B1 + 256*BKP*4)       // 221184 (216 KB)

__global__ __launch_bounds__(256) void tf32_gemm_cp(
    const float* __restrict__ A,
    const float* __restrict__ Bm,
    float* __restrict__ C,
    const float* __restrict__ bias,
    int M, int N, int K)
{
    extern __shared__ __align__(16) float smf[];
    const uint32_t sb = smem_u32(smf);
    const int tid = threadIdx.x;
    const int wid = tid >> 5;
    const int bm = blockIdx.y * 128;
    const int bn = blockIdx.x * 256;
    const int wm = (wid >> 2) * 64;          // 0 or 64
    const int wn = (wid & 3) * 64;           // 0..192

    wmma::fragment<wmma::accumulator, 16, 16, 8, float> acc[4][4];
    #pragma unroll
    for (int mi = 0; mi < 4; mi++)
        #pragma unroll
        for (int ni = 0; ni < 4; ni++)
            wmma::fill_fragment(acc[mi][ni], 0.0f);

    // ---- fold bias: acc += ones(0.125) @ biasT (8 k-terms, exact)
    if (bias) {
        float (*biasT)[8] = (float(*)[8])smf;    // 256x8, overlays buffers
        {
            float bv = bias[bn + tid];
            #pragma unroll
            for (int k = 0; k < 8; k++) biasT[tid][k] = bv;
        }
        __syncthreads();
        wmma::fragment<wmma::matrix_a, 16, 16, 8, wmma::precision::tf32,
                       wmma::row_major> af;
        wmma::fill_fragment(af, wmma::__float_to_tf32(0.125f));
        #pragma unroll
        for (int ni = 0; ni < 4; ni++) {
            wmma::fragment<wmma::matrix_b, 16, 16, 8, wmma::precision::tf32,
                           wmma::col_major> bf;
            wmma::load_matrix_sync(bf, &biasT[wn + ni * 16][0], 8);
            #pragma unroll
            for (int t = 0; t < bf.num_elements; t++)
                bf.x[t] = wmma::__float_to_tf32(bf.x[t]);
            #pragma unroll
            for (int mi = 0; mi < 4; mi++)
                wmma::mma_sync(acc[mi][ni], af, bf, acc[mi][ni]);
        }
        __syncthreads();
    }

    const float* Aptr = A  + (size_t)bm * K;
    const float* Bptr = Bm + (size_t)bn * K;
    const int nk = K / BKQ;

    // per-thread cp.async coords: 16 float4 per 64-float row
    const int sr = tid >> 4;                  // 0..15
    const int scol = (tid & 15) * 4;          // 0..60

    // issue one chunk's loads into buffer `buf`
    auto issue = [&](int kc, int buf) {
        const float* Ap = Aptr + kc * BKQ;
        const uint32_t abase = sb + (buf ? OFF_A1 : OFF_A0);
        #pragma unroll
        for (int i = 0; i < 8; i++) {
            int r = sr + i * 16;              // 0..127
            CP_ASYNC16(abase + (uint32_t)(r * BKP + scol) * 4,
                       Ap + (size_t)r * K + scol);
        }
        const float* Bp = Bptr + kc * BKQ;
        const uint32_t bbase = sb + (buf ? OFF_B1 : OFF_B0);
        #pragma unroll
        for (int i = 0; i < 16; i++) {
            int r = sr + i * 16;              // 0..255
            CP_ASYNC16(bbase + (uint32_t)(r * BKP + scol) * 4,
                       Bp + (size_t)r * K + scol);
        }
        CP_COMMIT();
    };

    issue(0, 0);

    for (int kc = 0; kc < nk; kc++) {
        const int cur = kc & 1;
        const bool hn = (kc + 1) < nk;
        if (hn) issue(kc + 1, cur ^ 1);
        if (hn) { CP_WAIT1(); } else { CP_WAIT0(); }
        __syncthreads();

        const float* Abuf = smf + (cur ? OFF_A1 : OFF_A0) / 4;
        const float* Bbuf = smf + (cur ? OFF_B1 : OFF_B0) / 4;

        #pragma unroll
        for (int ks = 0; ks < 8; ks++) {
            wmma::fragment<wmma::matrix_a, 16, 16, 8, wmma::precision::tf32,
                           wmma::row_major> af[4];
            wmma::fragment<wmma::matrix_b, 16, 16, 8, wmma::precision::tf32,
                           wmma::col_major> bf[4];
            #pragma unroll
            for (int mi = 0; mi < 4; mi++)
                wmma::load_matrix_sync(af[mi],
                    Abuf + (wm + mi * 16) * BKP + ks * 8, BKP);
            #pragma unroll
            for (int ni = 0; ni < 4; ni++)
                wmma::load_matrix_sync(bf[ni],
                    Bbuf + (wn + ni * 16) * BKP + ks * 8, BKP);
            #pragma unroll
            for (int mi = 0; mi < 4; mi++)
                #pragma unroll
                for (int ni = 0; ni < 4; ni++)
                    wmma::mma_sync(acc[mi][ni], af[mi], bf[ni], acc[mi][ni]);
        }
        __syncthreads();
    }

    #pragma unroll
    for (int mi = 0; mi < 4; mi++)
        #pragma unroll
        for (int ni = 0; ni < 4; ni++)
            wmma::store_matrix_sync(
                &C[(size_t)(bm + wm + mi * 16) * N + bn + wn + ni * 16],
                acc[mi][ni], N, wmma::mem_row_major);
}

// ---------------------------------------------------------------------------
// Context kernel: ctx[d][e] = sum_n softmax(k[n,:])[d] * v[n,e], split-K
// ---------------------------------------------------------------------------
__global__ __launch_bounds__(256) void ctx_kernel()
{
    const int pair  = blockIdx.x;
    const int chunk = blockIdx.y;
    const int b = pair >> 3, h = pair & 7;
    const int tid = threadIdx.x;

    __shared__ __align__(16) float sk[32][DH];
    __shared__ __align__(16) float sv[32][DH];

    const int d0 = (tid >> 4) * 4;
    const int e0 = (tid & 15) * 4;

    float acc[4][4];
    #pragma unroll
    for (int i = 0; i < 4; i++)
        #pragma unroll
        for (int j = 0; j < 4; j++) acc[i][j] = 0.f;

    const float* base = g_qkv + (size_t)b * NSEQ * N_QKV;
    const int n_begin = chunk * ROWS_PER_CHUNK;

    for (int n0 = n_begin; n0 < n_begin + ROWS_PER_CHUNK; n0 += 32) {
        #pragma unroll
        for (int i = 0; i < 2; i++) {
            int id = tid + i * 256;
            int r  = id >> 4;
            int c  = (id & 15) * 4;
            size_t off = (size_t)(n0 + r) * N_QKV + h * DH + c;
            *(float4*)&sk[r][c] = *(const float4*)(base + off + INNER);
            *(float4*)&sv[r][c] = *(const float4*)(base + off + 2 * INNER);
        }
        __syncthreads();

        {
            int r     = tid >> 3;
            int lane8 = tid & 7;
            float vals[8];
            float m = -1e30f;
            #pragma unroll
            for (int j = 0; j < 8; j++) {
                vals[j] = sk[r][lane8 * 8 + j];
                m = fmaxf(m, vals[j]);
            }
            #pragma unroll
            for (int s = 4; s >= 1; s >>= 1)
                m = fmaxf(m, __shfl_xor_sync(0xffffffffu, m, s));
            float sum = 0.f;
            #pragma unroll
            for (int j = 0; j < 8; j++) { vals[j] = __expf(vals[j] - m); sum += vals[j]; }
            #pragma unroll
            for (int s = 4; s >= 1; s >>= 1)
                sum += __shfl_xor_sync(0xffffffffu, sum, s);
            float inv = 1.0f / sum;
            #pragma unroll
            for (int j = 0; j < 8; j++)
                sk[r][lane8 * 8 + j] = vals[j] * inv;
        }
        __syncthreads();

        #pragma unroll 4
        for (int r = 0; r < 32; r++) {
            float4 kd = *(const float4*)&sk[r][d0];
            float4 ve = *(const float4*)&sv[r][e0];
            float kdv[4] = {kd.x, kd.y, kd.z, kd.w};
            float vev[4] = {ve.x, ve.y, ve.z, ve.w};
            #pragma unroll
            for (int i = 0; i < 4; i++)
                #pragma unroll
                for (int j = 0; j < 4; j++)
                    acc[i][j] += kdv[i] * vev[j];
        }
        __syncthreads();
    }

    float* out = g_ctxp + ((size_t)chunk * (B*HEADS) + pair) * DH * DH;
    #pragma unroll
    for (int i = 0; i < 4; i++) {
        float4 v = make_float4(acc[i][0], acc[i][1], acc[i][2], acc[i][3]);
        *(float4*)&out[(d0 + i) * DH + e0] = v;
    }
}

// ---------------------------------------------------------------------------
// Attention-apply; output rounded to tf32 (feeds GEMM4 directly)
// ---------------------------------------------------------------------------
__global__ __launch_bounds__(256) void attn_kernel()
{
    const int pair = blockIdx.x;
    const int b = pair >> 3, h = pair & 7;
    const int n0 = blockIdx.y * 128;
    const int tid = threadIdx.x;

    __shared__ __align__(16) float sctx[DH][DH];
    __shared__ __align__(16) float sq[128][DH];

    for (int idx = tid; idx < DH * DH; idx += 256) {
        float s = 0.f;
        #pragma unroll
        for (int ch = 0; ch < NCHUNK; ch++)
            s += g_ctxp[((size_t)ch * (B*HEADS) + pair) * DH * DH + idx];
        sctx[idx >> 6][idx & 63] = s;
    }

    const float* qbase = g_qkv + (size_t)b * NSEQ * N_QKV + h * DH;
    #pragma unroll
    for (int i = 0; i < 8; i++) {
        int id = tid + i * 256;
        int r  = id >> 4;
        int c  = (id & 15) * 4;
        *(float4*)&sq[r][c] =
            *(const float4*)(qbase + (size_t)(n0 + r) * N_QKV + c);
    }
    __syncthreads();

    const int e0 = (tid & 15) * 4;
    const int rg = tid >> 4;
    float acc[8][4];
    #pragma unroll
    for (int i = 0; i < 8; i++)
        #pragma unroll
        for (int j = 0; j < 4; j++) acc[i][j] = 0.f;

    #pragma unroll 8
    for (int d = 0; d < DH; d++) {
        float4 c4 = *(const float4*)&sctx[d][e0];
        float cv[4] = {c4.x, c4.y, c4.z, c4.w};
        #pragma unroll
        for (int i = 0; i < 8; i++) {
            float a = sq[rg + 16 * i][d];
            #pragma unroll
            for (int j = 0; j < 4; j++)
                acc[i][j] += a * cv[j];
        }
    }

    float* obase = g_attn + (size_t)(b * NSEQ + n0) * INNER + h * DH;
    #pragma unroll
    for (int i = 0; i < 8; i++) {
        int r = rg + 16 * i;
        float4 v = make_float4(to_tf32(acc[i][0]), to_tf32(acc[i][1]),
                               to_tf32(acc[i][2]), to_tf32(acc[i][3]));
        *(float4*)(obase + (size_t)r * INNER + e0) = v;
    }
}

// ---------------------------------------------------------------------------
extern "C" void kernel_launch(void* const* d_in, const int* in_sizes, int n_in,
                              void* d_out, int out_size)
{
    const float* x     = (const float*)d_in[0];   // [4,4096,1024]
    const float* w_qkv = (const float*)d_in[1];   // [1536,1024]
    const float* w_out = (const float*)d_in[2];   // [1024,512]
    const float* b_out = (const float*)d_in[3];   // [1024]
    float* out = (float*)d_out;                   // [4,4096,1024]

    float *qkv_p, *attn_p, *xc_p, *wqkvc_p, *woutc_p;
    cudaGetSymbolAddress((void**)&qkv_p,   g_qkv);
    cudaGetSymbolAddress((void**)&attn_p,  g_attn);
    cudaGetSymbolAddress((void**)&xc_p,    g_xc);
    cudaGetSymbolAddress((void**)&wqkvc_p, g_wqkvc);
    cudaGetSymbolAddress((void**)&woutc_p, g_woutc);

    cudaFuncSetAttribute(tf32_gemm_cp,
        cudaFuncAttributeMaxDynamicSharedMemorySize, SMEM_GEMM);

    // 0) round inputs to tf32 once (streaming)
    {
        int n4x = M_ROWS * DIM / 4;
        cvt_tf32_kernel<<<(n4x + 255) / 256, 256>>>(x, xc_p, n4x);
        int n4q = N_QKV * DIM / 4;
        cvt_tf32_kernel<<<(n4q + 255) / 256, 256>>>(w_qkv, wqkvc_p, n4q);
        int n4o = DIM * INNER / 4;
        cvt_tf32_kernel<<<(n4o + 255) / 256, 256>>>(w_out, woutc_p, n4o);
    }

    // 1) QKV projection: [16384,1536] = xc @ wqkvc^T
    tf32_gemm_cp<<<dim3(N_QKV / 256, M_ROWS / 128), 256, SMEM_GEMM>>>(
        xc_p, wqkvc_p, qkv_p, nullptr, M_ROWS, N_QKV, DIM);

    // 2) softmax(k) + context partials
    ctx_kernel<<<dim3(B * HEADS, NCHUNK), 256>>>();

    // 3) q @ context -> attn (tf32-rounded) [16384, 512]
    attn_kernel<<<dim3(B * HEADS, NSEQ / 128), 256>>>();

    // 4) output projection + bias: [16384,1024] = attn @ woutc^T + b_out
    tf32_gemm_cp<<<dim3(DIM / 256, M_ROWS / 128), 256, SMEM_GEMM>>>(
        attn_p, woutc_p, out, b_out, M_ROWS, DIM, INNER);
}